// round 2
// baseline (speedup 1.0000x reference)
#include <cuda_runtime.h>

// Equivariant linear: RS = [(16,0),(16,1),(16,2)], dim = 144, BATCH = 262144.
// W[i,j] is block-diagonal per (l, m): out[z, l, v, t] = sum_u Wl[v,u] * x[z, l, u, t]
// with Wl[v,u] = weight[l*256 + v*16 + u] * 0.25 / sqrt(2l+1).
// Layout within a row: l=0 at cols [0,16) (d=1), l=1 at [16,64) idx 16+u*3+t,
// l=2 at [64,144) idx 64+u*5+t.

#define ROWS_PER_BLOCK 64
#define ROW_STRIDE 145   // 144 padded: 145 mod 32 = 17 (odd) -> conflict-free lane spread
#define NTHREADS 256
#define DIM 144
#define VECS_PER_ROW 36  // 144 / 4

__global__ __launch_bounds__(NTHREADS) void eq_linear_kernel(
    const float* __restrict__ x,
    const float* __restrict__ w,
    float* __restrict__ y)
{
    __shared__ float sW[768];
    __shared__ float sD[ROWS_PER_BLOCK * ROW_STRIDE];

    const int tid = threadIdx.x;

    // Stage the three 16x16 mixing matrices, pre-scaled by cg * norm factor.
    // factor = 1/sqrt(num_summed/mul_out) = 1/sqrt(256/16) = 0.25
    // cg = 1/sqrt(2l+1)
    #pragma unroll
    for (int i = tid; i < 768; i += NTHREADS) {
        int l = i >> 8;
        float scale = (l == 0) ? 0.25f
                    : (l == 1) ? 0.25f * 0.57735026918962576f   // 1/sqrt(3)
                               : 0.25f * 0.44721359549995794f;  // 1/sqrt(5)
        sW[i] = w[i] * scale;
    }

    const long long row0 = (long long)blockIdx.x * ROWS_PER_BLOCK;
    const float4* __restrict__ in4 = reinterpret_cast<const float4*>(x) + row0 * VECS_PER_ROW;

    // Coalesced load of the tile: 64 rows x 36 float4.
    #pragma unroll
    for (int i = tid; i < ROWS_PER_BLOCK * VECS_PER_ROW; i += NTHREADS) {
        int r = i / VECS_PER_ROW;
        int c = i % VECS_PER_ROW;
        float4 v = in4[(long long)r * VECS_PER_ROW + c];
        float* d = sD + r * ROW_STRIDE + c * 4;
        d[0] = v.x; d[1] = v.y; d[2] = v.z; d[3] = v.w;
    }
    __syncthreads();

    // Compute: 9 m-slices x 64 rows. Each item: 16-vec gather (stride d),
    // 16x16 matvec, scatter back in place (independent per slice -> safe).
    // idx/64 -> slice is warp-uniform, W reads are broadcast.
    for (int idx = tid; idx < ROWS_PER_BLOCK * 9; idx += NTHREADS) {
        const int s = idx / ROWS_PER_BLOCK;
        const int r = idx % ROWS_PER_BLOCK;
        int l, off, d;
        if (s == 0)      { l = 0; off = 0;            d = 1; }
        else if (s < 4)  { l = 1; off = 16 + (s - 1); d = 3; }
        else             { l = 2; off = 64 + (s - 4); d = 5; }

        float* p = sD + r * ROW_STRIDE + off;

        float xv[16];
        #pragma unroll
        for (int u = 0; u < 16; u++) xv[u] = p[u * d];

        const float* W = sW + l * 256;
        float yv[16];
        #pragma unroll
        for (int v = 0; v < 16; v++) {
            float acc = 0.0f;
            #pragma unroll
            for (int u = 0; u < 16; u++)
                acc = fmaf(W[v * 16 + u], xv[u], acc);
            yv[v] = acc;
        }

        #pragma unroll
        for (int v = 0; v < 16; v++) p[v * d] = yv[v];
    }
    __syncthreads();

    // Coalesced store.
    float4* __restrict__ out4 = reinterpret_cast<float4*>(y) + row0 * VECS_PER_ROW;
    #pragma unroll
    for (int i = tid; i < ROWS_PER_BLOCK * VECS_PER_ROW; i += NTHREADS) {
        int r = i / VECS_PER_ROW;
        int c = i % VECS_PER_ROW;
        const float* d = sD + r * ROW_STRIDE + c * 4;
        out4[(long long)r * VECS_PER_ROW + c] = make_float4(d[0], d[1], d[2], d[3]);
    }
}

extern "C" void kernel_launch(void* const* d_in, const int* in_sizes, int n_in,
                              void* d_out, int out_size)
{
    // Inputs (metadata order): features [B*144] f32, weight [768] f32,
    // mixing_matrix (unused), norm_coef (unused).
    const float* feat = (const float*)d_in[0];
    const float* w    = (const float*)d_in[1];
    float* out        = (float*)d_out;

    const int batch  = in_sizes[0] / DIM;          // 262144
    const int blocks = batch / ROWS_PER_BLOCK;     // 4096

    eq_linear_kernel<<<blocks, NTHREADS>>>(feat, w, out);
}